// round 10
// baseline (speedup 1.0000x reference)
#include <cuda_runtime.h>
#include <cuda_bf16.h>
#include <cstdint>

#define DINL __device__ __forceinline__

namespace {
constexpr int   kBatch    = 524288;
constexpr int   kRowsCTA  = 128;                     // 4 warps x 32 rows (2 tiles of 16)
constexpr int   kNumTiles = kBatch / kRowsCTA;       // 4096
constexpr int   kThreads  = 128;
constexpr float kDT = 0.01f;

// SMEM offsets in uint32 units
constexpr int OFF_W2  = 0;      // W2  B-frags [8 ks][8 np][32 lane] uint4 -> 8192 u32
constexpr int OFF_W2T = 8192;   // W2^T B-frags, same layout              -> 8192 u32
constexpr int OFF_W1  = 16384;  // W1 k8 B-frags [8 np][32 lane] uint2    -> 512 u32
constexpr int OFF_W1T = 16896;  // W1^T B-frags [8 ks][32 lane] uint2     -> 512 u32
constexpr int OFF_B1  = 17408;  // f32[128]
constexpr int OFF_B2  = 17536;  // f32[128]
constexpr int OFF_W3  = 17664;  // f32[128]
constexpr int kSmemU32 = 17792; // 71168 bytes -> 2 CTAs/SM
}

DINL float tanh_fast(float x) { float r; asm("tanh.approx.f32 %0, %1;" : "=f"(r) : "f"(x)); return r; }

DINL uint32_t pack_bf2(float lo, float hi) {
    __nv_bfloat162 t = __floats2bfloat162_rn(lo, hi);
    return *reinterpret_cast<uint32_t*>(&t);
}
DINL float2 unpack_bf2(uint32_t u) {
    __nv_bfloat162 t = *reinterpret_cast<__nv_bfloat162*>(&u);
    return make_float2(__bfloat162float(t.x), __bfloat162float(t.y));
}

// D = A(16x16 bf16) x B(16x8 bf16) + D, fp32 accum
DINL void mma16816(float* c, uint32_t a0, uint32_t a1, uint32_t a2, uint32_t a3,
                   uint32_t b0, uint32_t b1) {
    asm volatile(
        "mma.sync.aligned.m16n8k16.row.col.f32.bf16.bf16.f32 "
        "{%0,%1,%2,%3}, {%4,%5,%6,%7}, {%8,%9}, {%0,%1,%2,%3};"
        : "+f"(c[0]), "+f"(c[1]), "+f"(c[2]), "+f"(c[3])
        : "r"(a0), "r"(a1), "r"(a2), "r"(a3), "r"(b0), "r"(b1));
}
// D = A(16x8 bf16) x B(8x8 bf16) + D (layer 1: true K = 8)
DINL void mma16808(float* c, uint32_t a0, uint32_t a1, uint32_t b0) {
    asm volatile(
        "mma.sync.aligned.m16n8k8.row.col.f32.bf16.bf16.f32 "
        "{%0,%1,%2,%3}, {%4,%5}, {%6}, {%0,%1,%2,%3};"
        : "+f"(c[0]), "+f"(c[1]), "+f"(c[2]), "+f"(c[3])
        : "r"(a0), "r"(a1), "r"(b0));
}

// -----------------------------------------------------------------------------
// grad_eval: 32 rows/warp = two 16-row tiles (A,B) sharing every B fragment
// (halves smem-crossbar bytes per FLOP — the measured binder at M=16).
// GEMMs processed in N-chunks of 4 nt, ks-outer inside the chunk: 8 independent
// HMMAs per ks step (ILP 8) with only 32 accumulator regs live.
// Backward elementwise overwrites hf in place (h1 dead after its tanh-deriv),
// so the live set is hf(64) + gf(64) + acc(32) + misc -> ~210 regs, no spills.
// -----------------------------------------------------------------------------
DINL void grad_eval(const uint4* __restrict__ w2f,  const uint4* __restrict__ w2tf,
                    const uint2* __restrict__ w1f,  const uint2* __restrict__ w1tf,
                    const float2* __restrict__ b1v, const float2* __restrict__ b2v,
                    const float2* __restrict__ w3v, int lane,
                    const float s0[4], const float s1[4], float d0[4], float d1[4]) {
    const int tg = lane & 3;
    const uint32_t azA0 = pack_bf2(s0[0], s0[1]), azA1 = pack_bf2(s0[2], s0[3]);
    const uint32_t azB0 = pack_bf2(s1[0], s1[1]), azB1 = pack_bf2(s1[2], s1[3]);
    uint32_t hfA[32], hfB[32];   // h1 A-frags (K=128), later overwritten by dpre1
    uint32_t gfA[32], gfB[32];   // dpre2 A-frags

    // ---- layer 1 (k8): h1 = tanh(z @ W1 + b1), chunked ----
#pragma unroll
    for (int c = 0; c < 4; c++) {
        float aA[16], aB[16];
#pragma unroll
        for (int i = 0; i < 16; i++) { aA[i] = 0.f; aB[i] = 0.f; }
#pragma unroll
        for (int j = 0; j < 2; j++) {                 // np = 2c + j -> nt 4c+2j, 4c+2j+1
            const uint2 b = w1f[(2 * c + j) * 32 + lane];
            mma16808(aA + 8 * j,     azA0, azA1, b.x);
            mma16808(aA + 8 * j + 4, azA0, azA1, b.y);
            mma16808(aB + 8 * j,     azB0, azB1, b.x);
            mma16808(aB + 8 * j + 4, azB0, azB1, b.y);
        }
#pragma unroll
        for (int j = 0; j < 4; j++) {                 // nt = 4c + j
            const int nt = 4 * c + j;
            const float2 bb = b1v[nt * 4 + tg];
            hfA[2*nt]   = pack_bf2(tanh_fast(aA[4*j]   + bb.x), tanh_fast(aA[4*j+1] + bb.y));
            hfA[2*nt+1] = pack_bf2(tanh_fast(aA[4*j+2] + bb.x), tanh_fast(aA[4*j+3] + bb.y));
            hfB[2*nt]   = pack_bf2(tanh_fast(aB[4*j]   + bb.x), tanh_fast(aB[4*j+1] + bb.y));
            hfB[2*nt+1] = pack_bf2(tanh_fast(aB[4*j+2] + bb.x), tanh_fast(aB[4*j+3] + bb.y));
        }
    }

    // ---- layer 2: dpre2 = w3 * (1 - tanh(h1 @ W2 + b2)^2), chunked ----
#pragma unroll
    for (int c = 0; c < 4; c++) {
        float aA[16], aB[16];
#pragma unroll
        for (int i = 0; i < 16; i++) { aA[i] = 0.f; aB[i] = 0.f; }
#pragma unroll
        for (int ks = 0; ks < 8; ks++) {
            const uint4 b0 = w2f[(ks * 8 + 2 * c)     * 32 + lane];
            const uint4 b1 = w2f[(ks * 8 + 2 * c + 1) * 32 + lane];
            mma16816(aA,      hfA[4*ks], hfA[4*ks+1], hfA[4*ks+2], hfA[4*ks+3], b0.x, b0.y);
            mma16816(aA + 4,  hfA[4*ks], hfA[4*ks+1], hfA[4*ks+2], hfA[4*ks+3], b0.z, b0.w);
            mma16816(aA + 8,  hfA[4*ks], hfA[4*ks+1], hfA[4*ks+2], hfA[4*ks+3], b1.x, b1.y);
            mma16816(aA + 12, hfA[4*ks], hfA[4*ks+1], hfA[4*ks+2], hfA[4*ks+3], b1.z, b1.w);
            mma16816(aB,      hfB[4*ks], hfB[4*ks+1], hfB[4*ks+2], hfB[4*ks+3], b0.x, b0.y);
            mma16816(aB + 4,  hfB[4*ks], hfB[4*ks+1], hfB[4*ks+2], hfB[4*ks+3], b0.z, b0.w);
            mma16816(aB + 8,  hfB[4*ks], hfB[4*ks+1], hfB[4*ks+2], hfB[4*ks+3], b1.x, b1.y);
            mma16816(aB + 12, hfB[4*ks], hfB[4*ks+1], hfB[4*ks+2], hfB[4*ks+3], b1.z, b1.w);
        }
#pragma unroll
        for (int j = 0; j < 4; j++) {
            const int nt = 4 * c + j;
            const float2 bb = b2v[nt * 4 + tg];
            const float2 ww = w3v[nt * 4 + tg];
            float t0, t1;
            t0 = tanh_fast(aA[4*j]   + bb.x); t1 = tanh_fast(aA[4*j+1] + bb.y);
            gfA[2*nt]   = pack_bf2(ww.x * (1.f - t0*t0), ww.y * (1.f - t1*t1));
            t0 = tanh_fast(aA[4*j+2] + bb.x); t1 = tanh_fast(aA[4*j+3] + bb.y);
            gfA[2*nt+1] = pack_bf2(ww.x * (1.f - t0*t0), ww.y * (1.f - t1*t1));
            t0 = tanh_fast(aB[4*j]   + bb.x); t1 = tanh_fast(aB[4*j+1] + bb.y);
            gfB[2*nt]   = pack_bf2(ww.x * (1.f - t0*t0), ww.y * (1.f - t1*t1));
            t0 = tanh_fast(aB[4*j+2] + bb.x); t1 = tanh_fast(aB[4*j+3] + bb.y);
            gfB[2*nt+1] = pack_bf2(ww.x * (1.f - t0*t0), ww.y * (1.f - t1*t1));
        }
    }

    // ---- layer 3: dpre1 = (dpre2 @ W2^T) * (1 - h1^2), chunked, hf overwritten ----
#pragma unroll
    for (int c = 0; c < 4; c++) {
        float aA[16], aB[16];
#pragma unroll
        for (int i = 0; i < 16; i++) { aA[i] = 0.f; aB[i] = 0.f; }
#pragma unroll
        for (int ks = 0; ks < 8; ks++) {
            const uint4 b0 = w2tf[(ks * 8 + 2 * c)     * 32 + lane];
            const uint4 b1 = w2tf[(ks * 8 + 2 * c + 1) * 32 + lane];
            mma16816(aA,      gfA[4*ks], gfA[4*ks+1], gfA[4*ks+2], gfA[4*ks+3], b0.x, b0.y);
            mma16816(aA + 4,  gfA[4*ks], gfA[4*ks+1], gfA[4*ks+2], gfA[4*ks+3], b0.z, b0.w);
            mma16816(aA + 8,  gfA[4*ks], gfA[4*ks+1], gfA[4*ks+2], gfA[4*ks+3], b1.x, b1.y);
            mma16816(aA + 12, gfA[4*ks], gfA[4*ks+1], gfA[4*ks+2], gfA[4*ks+3], b1.z, b1.w);
            mma16816(aB,      gfB[4*ks], gfB[4*ks+1], gfB[4*ks+2], gfB[4*ks+3], b0.x, b0.y);
            mma16816(aB + 4,  gfB[4*ks], gfB[4*ks+1], gfB[4*ks+2], gfB[4*ks+3], b0.z, b0.w);
            mma16816(aB + 8,  gfB[4*ks], gfB[4*ks+1], gfB[4*ks+2], gfB[4*ks+3], b1.x, b1.y);
            mma16816(aB + 12, gfB[4*ks], gfB[4*ks+1], gfB[4*ks+2], gfB[4*ks+3], b1.z, b1.w);
        }
#pragma unroll
        for (int j = 0; j < 4; j++) {
            const int nt = 4 * c + j;
            float2 hh;
            hh = unpack_bf2(hfA[2*nt]);
            hfA[2*nt]   = pack_bf2(aA[4*j]   * (1.f - hh.x*hh.x), aA[4*j+1] * (1.f - hh.y*hh.y));
            hh = unpack_bf2(hfA[2*nt+1]);
            hfA[2*nt+1] = pack_bf2(aA[4*j+2] * (1.f - hh.x*hh.x), aA[4*j+3] * (1.f - hh.y*hh.y));
            hh = unpack_bf2(hfB[2*nt]);
            hfB[2*nt]   = pack_bf2(aB[4*j]   * (1.f - hh.x*hh.x), aB[4*j+1] * (1.f - hh.y*hh.y));
            hh = unpack_bf2(hfB[2*nt+1]);
            hfB[2*nt+1] = pack_bf2(aB[4*j+2] * (1.f - hh.x*hh.x), aB[4*j+3] * (1.f - hh.y*hh.y));
        }
    }

    // ---- layer 4: dz = dpre1 @ W1^T ----
    d0[0] = d0[1] = d0[2] = d0[3] = 0.f;
    d1[0] = d1[1] = d1[2] = d1[3] = 0.f;
#pragma unroll
    for (int ks = 0; ks < 8; ks++) {
        const uint2 bw = w1tf[ks * 32 + lane];
        mma16816(d0, hfA[4*ks], hfA[4*ks+1], hfA[4*ks+2], hfA[4*ks+3], bw.x, bw.y);
        mma16816(d1, hfB[4*ks], hfB[4*ks+1], hfB[4*ks+2], hfB[4*ks+3], bw.x, bw.y);
    }
}

// -----------------------------------------------------------------------------
__global__ void __launch_bounds__(kThreads, 2)
symp_kernel(const float* __restrict__ z,  const float* __restrict__ W1,
            const float* __restrict__ b1, const float* __restrict__ W2,
            const float* __restrict__ b2, const float* __restrict__ W3,
            const float* __restrict__ b3, float* __restrict__ out) {
    extern __shared__ uint32_t sm[];
    const int tid = threadIdx.x;
    const int wid = tid >> 5, lane = tid & 31;

    // ---- build weight B-fragments in SMEM (once per persistent CTA) ----
    for (int idx = tid; idx < 8 * 8 * 32; idx += kThreads) {
        int ks = idx >> 8, np = (idx >> 5) & 7, ln = idx & 31;
        int n0 = (2 * np) * 8 + (ln >> 2);
        int n1 = n0 + 8;
        int kb = ks * 16 + (ln & 3) * 2;
        ((uint4*)(sm + OFF_W2))[idx] = make_uint4(
            pack_bf2(W2[kb * 128 + n0],       W2[(kb + 1) * 128 + n0]),
            pack_bf2(W2[(kb + 8) * 128 + n0], W2[(kb + 9) * 128 + n0]),
            pack_bf2(W2[kb * 128 + n1],       W2[(kb + 1) * 128 + n1]),
            pack_bf2(W2[(kb + 8) * 128 + n1], W2[(kb + 9) * 128 + n1]));
        ((uint4*)(sm + OFF_W2T))[idx] = make_uint4(
            pack_bf2(W2[n0 * 128 + kb],     W2[n0 * 128 + kb + 1]),
            pack_bf2(W2[n0 * 128 + kb + 8], W2[n0 * 128 + kb + 9]),
            pack_bf2(W2[n1 * 128 + kb],     W2[n1 * 128 + kb + 1]),
            pack_bf2(W2[n1 * 128 + kb + 8], W2[n1 * 128 + kb + 9]));
    }
    for (int idx = tid; idx < 8 * 32; idx += kThreads) {    // W1 k8 frag pairs
        int np = idx >> 5, ln = idx & 31;
        int n0 = (2 * np) * 8 + (ln >> 2);
        int n1 = n0 + 8;
        int kb = (ln & 3) * 2;
        ((uint2*)(sm + OFF_W1))[idx] = make_uint2(
            pack_bf2(W1[kb * 128 + n0], W1[(kb + 1) * 128 + n0]),
            pack_bf2(W1[kb * 128 + n1], W1[(kb + 1) * 128 + n1]));
    }
    for (int idx = tid; idx < 8 * 32; idx += kThreads) {    // W1^T: B(k,n) = W1[n*128+k]
        int ks = idx >> 5, ln = idx & 31;
        int n  = ln >> 2;
        int kb = ks * 16 + (ln & 3) * 2;
        ((uint2*)(sm + OFF_W1T))[idx] = make_uint2(
            pack_bf2(W1[n * 128 + kb],     W1[n * 128 + kb + 1]),
            pack_bf2(W1[n * 128 + kb + 8], W1[n * 128 + kb + 9]));
    }
    ((float*)(sm + OFF_B1))[tid] = b1[tid];
    ((float*)(sm + OFF_B2))[tid] = b2[tid];
    ((float*)(sm + OFF_W3))[tid] = W3[tid];
    __syncthreads();

    const uint4*  w2f  = (const uint4*)(sm + OFF_W2);
    const uint4*  w2tf = (const uint4*)(sm + OFF_W2T);
    const uint2*  w1f  = (const uint2*)(sm + OFF_W1);
    const uint2*  w1tf = (const uint2*)(sm + OFF_W1T);
    const float2* b1v  = (const float2*)(sm + OFF_B1);
    const float2* b2v  = (const float2*)(sm + OFF_B2);
    const float2* w3v  = (const float2*)(sm + OFF_W3);
    (void)b3;  // constant offset: no effect on gradient

    const int gp = lane >> 2, tg = lane & 3;

    for (int t = blockIdx.x; t < kNumTiles; t += gridDim.x) {
        const int row0 = t * kRowsCTA + wid * 32;
        const float* zp0 = z + (size_t)(row0 + gp) * 8 + tg * 2;
        const float* zp1 = z + (size_t)(row0 + 16 + gp) * 8 + tg * 2;
        float s0[4], s1[4];
        {
            float2 v0 = *(const float2*)zp0, v1 = *(const float2*)(zp0 + 64);
            s0[0] = v0.x; s0[1] = v0.y; s0[2] = v1.x; s0[3] = v1.y;
            float2 u0 = *(const float2*)zp1, u1 = *(const float2*)(zp1 + 64);
            s1[0] = u0.x; s1[1] = u0.y; s1[2] = u1.x; s1[3] = u1.y;
        }
        float d0[4], d1[4];
#pragma unroll 1
        for (int it = 0; it < 4; it++) {
            grad_eval(w2f, w2tf, w1f, w1tf, b1v, b2v, w3v, lane, s0, s1, d0, d1);
            float w0[4], w1s[4];
#pragma unroll
            for (int i = 0; i < 4; i++) {
                w0[i]  = __shfl_xor_sync(0xffffffffu, d0[i], 2);
                w1s[i] = __shfl_xor_sync(0xffffffffu, d1[i], 2);
            }
            if ((it & 1) == 0) {
                if (tg < 2) {               // q cols: q += dt * dHdp
#pragma unroll
                    for (int i = 0; i < 4; i++) { s0[i] += kDT * w0[i]; s1[i] += kDT * w1s[i]; }
                } else {                    // p cols: p -= dt/2 * dHdq
#pragma unroll
                    for (int i = 0; i < 4; i++) { s0[i] -= 0.5f * kDT * w0[i]; s1[i] -= 0.5f * kDT * w1s[i]; }
                }
            } else {
                if (tg >= 2) {              // p cols: p = p_half - dt/2 * dHdq_new
#pragma unroll
                    for (int i = 0; i < 4; i++) { s0[i] -= 0.5f * kDT * w0[i]; s1[i] -= 0.5f * kDT * w1s[i]; }
                }
            }
        }
        float* op0 = out + (size_t)(row0 + gp) * 8 + tg * 2;
        float* op1 = out + (size_t)(row0 + 16 + gp) * 8 + tg * 2;
        *(float2*)op0        = make_float2(s0[0], s0[1]);
        *(float2*)(op0 + 64) = make_float2(s0[2], s0[3]);
        *(float2*)op1        = make_float2(s1[0], s1[1]);
        *(float2*)(op1 + 64) = make_float2(s1[2], s1[3]);
    }
}

extern "C" void kernel_launch(void* const* d_in, const int* in_sizes, int n_in,
                              void* d_out, int out_size) {
    const float* z  = (const float*)d_in[0];
    const float* W1 = (const float*)d_in[1];
    const float* b1 = (const float*)d_in[2];
    const float* W2 = (const float*)d_in[3];
    const float* b2 = (const float*)d_in[4];
    const float* W3 = (const float*)d_in[5];
    const float* b3 = (const float*)d_in[6];
    constexpr int kSmemBytes = kSmemU32 * 4;
    cudaFuncSetAttribute(symp_kernel, cudaFuncAttributeMaxDynamicSharedMemorySize, kSmemBytes);
    int grid = 296;                       // 2 persistent CTAs / SM x 148 SMs
    if (grid > kNumTiles) grid = kNumTiles;
    symp_kernel<<<grid, kThreads, kSmemBytes>>>(z, W1, b1, W2, b2, W3, b3, (float*)d_out);
    (void)in_sizes; (void)n_in; (void)out_size;
}

// round 11
// speedup vs baseline: 1.1729x; 1.1729x over previous
#include <cuda_runtime.h>
#include <cuda_bf16.h>
#include <cstdint>

#define DINL __device__ __forceinline__

namespace {
constexpr int   kBatch    = 524288;
constexpr int   kRowsCTA  = 64;                      // 4 warps x 16 rows
constexpr int   kNumTiles = kBatch / kRowsCTA;       // 8192
constexpr int   kThreads  = 128;
constexpr float kDT = 0.01f;

// SMEM offsets in uint32 units
constexpr int OFF_W2   = 0;      // W2  B-frags [8 ks][8 np][32 lane] uint4 -> 8192 u32
constexpr int OFF_W2T  = 8192;   // W2^T B-frags, same layout               -> 8192 u32
constexpr int OFF_W1   = 16384;  // W1 k8 B-frags [8 np][32 lane] uint2     -> 512 u32
constexpr int OFF_W1T  = 16896;  // W1^T B-frags [8 ks][32 lane] uint2      -> 512 u32
constexpr int OFF_B1   = 17408;  // f32[128]
constexpr int OFF_B2   = 17536;  // f32[128]
constexpr int OFF_W3B  = 17664;  // bf16x2[64]  (+W3 pairs)
constexpr int OFF_NW3B = 17728;  // bf16x2[64]  (-W3 pairs)
constexpr int kSmemU32 = 17792;  // 71168 bytes -> 2 CTAs/SM
}

DINL uint32_t pack_bf2(float lo, float hi) {
    __nv_bfloat162 t = __floats2bfloat162_rn(lo, hi);
    return *reinterpret_cast<uint32_t*>(&t);
}
// bf16x2 vector ops (HFMA2/MUFU pipes, sm_90+ PTX, no 'a'-suffix features)
DINL uint32_t tanh2(uint32_t x) { uint32_t r; asm("tanh.approx.bf16x2 %0, %1;" : "=r"(r) : "r"(x)); return r; }
DINL uint32_t mul2(uint32_t a, uint32_t b) { uint32_t r; asm("mul.rn.bf16x2 %0, %1, %2;" : "=r"(r) : "r"(a), "r"(b)); return r; }
DINL uint32_t fma2(uint32_t a, uint32_t b, uint32_t c) { uint32_t r; asm("fma.rn.bf16x2 %0, %1, %2, %3;" : "=r"(r) : "r"(a), "r"(b), "r"(c)); return r; }
DINL uint32_t neg2(uint32_t a) { uint32_t r; asm("neg.bf16x2 %0, %1;" : "=r"(r) : "r"(a)); return r; }

// D = A(16x16 bf16) x B(16x8 bf16) + D, fp32 accum
DINL void mma16816(float* c, uint32_t a0, uint32_t a1, uint32_t a2, uint32_t a3,
                   uint32_t b0, uint32_t b1) {
    asm volatile(
        "mma.sync.aligned.m16n8k16.row.col.f32.bf16.bf16.f32 "
        "{%0,%1,%2,%3}, {%4,%5,%6,%7}, {%8,%9}, {%0,%1,%2,%3};"
        : "+f"(c[0]), "+f"(c[1]), "+f"(c[2]), "+f"(c[3])
        : "r"(a0), "r"(a1), "r"(a2), "r"(a3), "r"(b0), "r"(b1));
}
// D = A(16x8 bf16) x B(8x8 bf16) + D (layer 1: true K = 8)
DINL void mma16808(float* c, uint32_t a0, uint32_t a1, uint32_t b0) {
    asm volatile(
        "mma.sync.aligned.m16n8k8.row.col.f32.bf16.bf16.f32 "
        "{%0,%1,%2,%3}, {%4,%5}, {%6}, {%0,%1,%2,%3};"
        : "+f"(c[0]), "+f"(c[1]), "+f"(c[2]), "+f"(c[3])
        : "r"(a0), "r"(a1), "r"(b0));
}

// -----------------------------------------------------------------------------
// grad_eval: 16 rows/warp, ks-outer GEMMs (16-way HMMA ILP), and ALL
// nonlinearities computed in bf16x2 (tanh.approx.bf16x2 + HFMA2 ops):
// halves the MUFU instruction count, which measurement shows serializes
// with the tensor phase (tensor busy 243us + MUFU busy 126us = 369us total).
// State s[4] / grad d[4] are C-fragments (rows g,g+8 / cols 2tg,2tg+1).
// -----------------------------------------------------------------------------
DINL void grad_eval(const uint4* __restrict__ w2f,  const uint4* __restrict__ w2tf,
                    const uint2* __restrict__ w1f,  const uint2* __restrict__ w1tf,
                    const float2* __restrict__ b1v, const float2* __restrict__ b2v,
                    const uint32_t* __restrict__ w3b, const uint32_t* __restrict__ nw3b,
                    int lane, const float s[4], float d[4]) {
    const int tg = lane & 3;
    const uint32_t az0 = pack_bf2(s[0], s[1]);   // row g,   k=2tg..2tg+1
    const uint32_t az1 = pack_bf2(s[2], s[3]);   // row g+8
    float acc[64];
    uint32_t hf[32];   // h1 as A-fragments (K=128)
    uint32_t gf[32];   // dpre2 / dpre1 as A-fragments

    // ---- layer 1 (k8): pre1 = z @ W1, 16 independent mmas ----
#pragma unroll
    for (int i = 0; i < 64; i++) acc[i] = 0.f;
#pragma unroll
    for (int np = 0; np < 8; np++) {
        const uint2 b = w1f[np * 32 + lane];
        mma16808(acc + 8 * np,     az0, az1, b.x);
        mma16808(acc + 8 * np + 4, az0, az1, b.y);
    }
    // h1 = tanh(pre1 + b1), tanh in bf16x2 (output already packed)
#pragma unroll
    for (int nt = 0; nt < 16; nt++) {
        const float2 bb = b1v[nt * 4 + tg];
        hf[2*nt]   = tanh2(pack_bf2(acc[4*nt]   + bb.x, acc[4*nt+1] + bb.y));
        hf[2*nt+1] = tanh2(pack_bf2(acc[4*nt+2] + bb.x, acc[4*nt+3] + bb.y));
    }

    // ---- layer 2: pre2 = h1 @ W2 (ks-outer, 16-way ILP) ----
#pragma unroll
    for (int i = 0; i < 64; i++) acc[i] = 0.f;
#pragma unroll
    for (int ks = 0; ks < 8; ks++) {
        const uint32_t a0 = hf[4*ks], a1 = hf[4*ks+1], a2 = hf[4*ks+2], a3 = hf[4*ks+3];
#pragma unroll
        for (int np = 0; np < 8; np++) {
            const uint4 b = w2f[(ks * 8 + np) * 32 + lane];
            mma16816(acc + 8 * np,     a0, a1, a2, a3, b.x, b.y);
            mma16816(acc + 8 * np + 4, a0, a1, a2, a3, b.z, b.w);
        }
    }
    // dpre2 = w3 * (1 - tanh(pre2 + b2)^2) = fma(-w3, t*t, w3), all bf16x2
#pragma unroll
    for (int nt = 0; nt < 16; nt++) {
        const float2 bb = b2v[nt * 4 + tg];
        const uint32_t w3p  = w3b[nt * 4 + tg];
        const uint32_t nw3p = nw3b[nt * 4 + tg];
        uint32_t t0 = tanh2(pack_bf2(acc[4*nt]   + bb.x, acc[4*nt+1] + bb.y));
        uint32_t t1 = tanh2(pack_bf2(acc[4*nt+2] + bb.x, acc[4*nt+3] + bb.y));
        gf[2*nt]   = fma2(nw3p, mul2(t0, t0), w3p);
        gf[2*nt+1] = fma2(nw3p, mul2(t1, t1), w3p);
    }

    // ---- layer 3: dh1 = dpre2 @ W2^T (ks-outer, 16-way ILP) ----
#pragma unroll
    for (int i = 0; i < 64; i++) acc[i] = 0.f;
#pragma unroll
    for (int ks = 0; ks < 8; ks++) {
        const uint32_t a0 = gf[4*ks], a1 = gf[4*ks+1], a2 = gf[4*ks+2], a3 = gf[4*ks+3];
#pragma unroll
        for (int np = 0; np < 8; np++) {
            const uint4 b = w2tf[(ks * 8 + np) * 32 + lane];
            mma16816(acc + 8 * np,     a0, a1, a2, a3, b.x, b.y);
            mma16816(acc + 8 * np + 4, a0, a1, a2, a3, b.z, b.w);
        }
    }
    // dpre1 = dh1 * (1 - h1^2) = fma(-v, h*h, v), all bf16x2 (reuse gf)
#pragma unroll
    for (int nt = 0; nt < 16; nt++) {
        uint32_t v0 = pack_bf2(acc[4*nt],   acc[4*nt+1]);
        uint32_t v1 = pack_bf2(acc[4*nt+2], acc[4*nt+3]);
        const uint32_t h0 = hf[2*nt], h1 = hf[2*nt+1];
        gf[2*nt]   = fma2(neg2(v0), mul2(h0, h0), v0);
        gf[2*nt+1] = fma2(neg2(v1), mul2(h1, h1), v1);
    }

    // ---- layer 4: dz = dpre1 @ W1^T ----
    d[0] = d[1] = d[2] = d[3] = 0.f;
#pragma unroll
    for (int ks = 0; ks < 8; ks++) {
        const uint2 bw = w1tf[ks * 32 + lane];
        mma16816(d, gf[4*ks], gf[4*ks+1], gf[4*ks+2], gf[4*ks+3], bw.x, bw.y);
    }
}

// -----------------------------------------------------------------------------
__global__ void __launch_bounds__(kThreads, 2)
symp_kernel(const float* __restrict__ z,  const float* __restrict__ W1,
            const float* __restrict__ b1, const float* __restrict__ W2,
            const float* __restrict__ b2, const float* __restrict__ W3,
            const float* __restrict__ b3, float* __restrict__ out) {
    extern __shared__ uint32_t sm[];
    const int tid = threadIdx.x;
    const int wid = tid >> 5, lane = tid & 31;

    // ---- build weight B-fragments in SMEM (once per persistent CTA) ----
    for (int idx = tid; idx < 8 * 8 * 32; idx += kThreads) {
        int ks = idx >> 8, np = (idx >> 5) & 7, ln = idx & 31;
        int n0 = (2 * np) * 8 + (ln >> 2);
        int n1 = n0 + 8;
        int kb = ks * 16 + (ln & 3) * 2;
        ((uint4*)(sm + OFF_W2))[idx] = make_uint4(
            pack_bf2(W2[kb * 128 + n0],       W2[(kb + 1) * 128 + n0]),
            pack_bf2(W2[(kb + 8) * 128 + n0], W2[(kb + 9) * 128 + n0]),
            pack_bf2(W2[kb * 128 + n1],       W2[(kb + 1) * 128 + n1]),
            pack_bf2(W2[(kb + 8) * 128 + n1], W2[(kb + 9) * 128 + n1]));
        ((uint4*)(sm + OFF_W2T))[idx] = make_uint4(
            pack_bf2(W2[n0 * 128 + kb],     W2[n0 * 128 + kb + 1]),
            pack_bf2(W2[n0 * 128 + kb + 8], W2[n0 * 128 + kb + 9]),
            pack_bf2(W2[n1 * 128 + kb],     W2[n1 * 128 + kb + 1]),
            pack_bf2(W2[n1 * 128 + kb + 8], W2[n1 * 128 + kb + 9]));
    }
    for (int idx = tid; idx < 8 * 32; idx += kThreads) {    // W1 k8 frag pairs
        int np = idx >> 5, ln = idx & 31;
        int n0 = (2 * np) * 8 + (ln >> 2);
        int n1 = n0 + 8;
        int kb = (ln & 3) * 2;
        ((uint2*)(sm + OFF_W1))[idx] = make_uint2(
            pack_bf2(W1[kb * 128 + n0], W1[(kb + 1) * 128 + n0]),
            pack_bf2(W1[kb * 128 + n1], W1[(kb + 1) * 128 + n1]));
    }
    for (int idx = tid; idx < 8 * 32; idx += kThreads) {    // W1^T: B(k,n) = W1[n*128+k]
        int ks = idx >> 5, ln = idx & 31;
        int n  = ln >> 2;
        int kb = ks * 16 + (ln & 3) * 2;
        ((uint2*)(sm + OFF_W1T))[idx] = make_uint2(
            pack_bf2(W1[n * 128 + kb],     W1[n * 128 + kb + 1]),
            pack_bf2(W1[n * 128 + kb + 8], W1[n * 128 + kb + 9]));
    }
    ((float*)(sm + OFF_B1))[tid] = b1[tid];
    ((float*)(sm + OFF_B2))[tid] = b2[tid];
    if (tid < 64) {
        sm[OFF_W3B  + tid] = pack_bf2( W3[2 * tid],  W3[2 * tid + 1]);
        sm[OFF_NW3B + tid] = pack_bf2(-W3[2 * tid], -W3[2 * tid + 1]);
    }
    __syncthreads();

    const uint4*    w2f  = (const uint4*)(sm + OFF_W2);
    const uint4*    w2tf = (const uint4*)(sm + OFF_W2T);
    const uint2*    w1f  = (const uint2*)(sm + OFF_W1);
    const uint2*    w1tf = (const uint2*)(sm + OFF_W1T);
    const float2*   b1v  = (const float2*)(sm + OFF_B1);
    const float2*   b2v  = (const float2*)(sm + OFF_B2);
    const uint32_t* w3b  = (const uint32_t*)(sm + OFF_W3B);
    const uint32_t* nw3b = (const uint32_t*)(sm + OFF_NW3B);
    (void)b3;  // constant offset: no effect on gradient

    const int gp = lane >> 2, tg = lane & 3;

    for (int t = blockIdx.x; t < kNumTiles; t += gridDim.x) {
        const int row0 = t * kRowsCTA + wid * 16;
        const float* zp = z + (size_t)(row0 + gp) * 8 + tg * 2;
        float s[4];
        {
            float2 v0 = *(const float2*)zp;          // row g
            float2 v1 = *(const float2*)(zp + 64);   // row g+8
            s[0] = v0.x; s[1] = v0.y; s[2] = v1.x; s[3] = v1.y;
        }
        float d[4], dsw[4];
#pragma unroll 1
        for (int it = 0; it < 4; it++) {
            grad_eval(w2f, w2tf, w1f, w1tf, b1v, b2v, w3b, nw3b, lane, s, d);
#pragma unroll
            for (int i = 0; i < 4; i++) dsw[i] = __shfl_xor_sync(0xffffffffu, d[i], 2);
            if ((it & 1) == 0) {
                if (tg < 2) {               // q cols: q += dt * dHdp
#pragma unroll
                    for (int i = 0; i < 4; i++) s[i] += kDT * dsw[i];
                } else {                    // p cols: p -= dt/2 * dHdq
#pragma unroll
                    for (int i = 0; i < 4; i++) s[i] -= 0.5f * kDT * dsw[i];
                }
            } else {
                if (tg >= 2) {              // p cols: p = p_half - dt/2 * dHdq_new
#pragma unroll
                    for (int i = 0; i < 4; i++) s[i] -= 0.5f * kDT * dsw[i];
                }
            }
        }
        float* op = out + (size_t)(row0 + gp) * 8 + tg * 2;
        *(float2*)op        = make_float2(s[0], s[1]);
        *(float2*)(op + 64) = make_float2(s[2], s[3]);
    }
}

extern "C" void kernel_launch(void* const* d_in, const int* in_sizes, int n_in,
                              void* d_out, int out_size) {
    const float* z  = (const float*)d_in[0];
    const float* W1 = (const float*)d_in[1];
    const float* b1 = (const float*)d_in[2];
    const float* W2 = (const float*)d_in[3];
    const float* b2 = (const float*)d_in[4];
    const float* W3 = (const float*)d_in[5];
    const float* b3 = (const float*)d_in[6];
    constexpr int kSmemBytes = kSmemU32 * 4;
    cudaFuncSetAttribute(symp_kernel, cudaFuncAttributeMaxDynamicSharedMemorySize, kSmemBytes);
    int grid = 296;                       // 2 persistent CTAs / SM x 148 SMs
    if (grid > kNumTiles) grid = kNumTiles;
    symp_kernel<<<grid, kThreads, kSmemBytes>>>(z, W1, b1, W2, b2, W3, b3, (float*)d_out);
    (void)in_sizes; (void)n_in; (void)out_size;
}